// round 13
// baseline (speedup 1.0000x reference)
#include <cuda_runtime.h>
#include <cuda_bf16.h>
#include <cstdint>

// out[b,r] = sum_k Xa[b,k]*G[k,r] + C[r]   (Gaussian NB log-likelihood as GEMM)
//   Xa[b,k] = x[b,k] (k<512), x[b,k-512]^2 (k>=512), x = concat(sbjs, objs)
//   G[k,r]  = mu[r,k]/sig^2 (k<512), -0.5/sig^2 (k>=512)
//   C[r]    = sum_d(-0.5*mu^2/sig^2 - log sig) - 512*LOG_SQRT_2PI + 512*prior[r]
// TWO kERNELS ONLY:
//   nb_mma:    BM64 x BN128 (full N), K-split x4 over x-columns. Each CTA
//              generates BOTH its A tile (from sbjs/objs, fp32->bf16 + square)
//              and its B tile (from mus/sigmas, L2-resident) directly in smem.
//              mt<8 CTAs also compute C partials (16 relations each).
//   nb_reduce: fixed-order sum of 4 partials + C(4 ks-parts) + prior.

#define BATCH 4096
#define EMB   256
#define TWO_D 512
#define NREL  128
#define KDIM  1024
#define KSPLIT 4

#define ROWB    144                 // smem row pitch (64 halves + 8 pad)
#define A_CHUNK (64 * ROWB)         // 9216 B  (64 batch rows x 64 halves)
#define B_CHUNK (128 * ROWB)        // 18432 B (128 relations x 64 halves)
#define A_ALL   (4 * A_CHUNK)       // 36864
#define SMEM_MMA (4 * A_CHUNK + 4 * B_CHUNK)   // 110592 B

__device__ float g_Cpart[KSPLIT * NREL];              // per-ks C partials
__device__ float g_partial[KSPLIT * BATCH * NREL];    // 8 MB scratch

__device__ __forceinline__ uint32_t smem_u32(const void* p) {
    uint32_t a;
    asm("{ .reg .u64 t; cvta.to.shared.u64 t, %1; cvt.u32.u64 %0, t; }"
        : "=r"(a) : "l"(p));
    return a;
}

#define LDSM4(r, addr) \
    asm volatile("ldmatrix.sync.aligned.m8n8.x4.shared.b16 {%0,%1,%2,%3}, [%4];" \
        : "=r"((r)[0]), "=r"((r)[1]), "=r"((r)[2]), "=r"((r)[3]) : "r"(addr))

__device__ __forceinline__ void mma16816(float* c, const uint32_t* a,
                                         uint32_t b0, uint32_t b1) {
    asm("mma.sync.aligned.m16n8k16.row.col.f32.bf16.bf16.f32 "
        "{%0,%1,%2,%3}, {%4,%5,%6,%7}, {%8,%9}, {%0,%1,%2,%3};"
        : "+f"(c[0]), "+f"(c[1]), "+f"(c[2]), "+f"(c[3])
        : "r"(a[0]), "r"(a[1]), "r"(a[2]), "r"(a[3]), "r"(b0), "r"(b1));
}

#define STS8(addr, v) \
    asm volatile("st.shared.v2.b32 [%0], {%1,%2};" :: \
        "r"(addr), "r"((v).x), "r"((v).y))
#define STS16(addr, v) \
    asm volatile("st.shared.v4.b32 [%0], {%1,%2,%3,%4};" :: \
        "r"(addr), "r"((v).x), "r"((v).y), "r"((v).z), "r"((v).w))

__device__ __forceinline__ uint32_t bf2pack(float a, float b) {
    __nv_bfloat162 h = __float22bfloat162_rn(make_float2(a, b));
    return *reinterpret_cast<uint32_t*>(&h);
}

// ---------------------------------------------------------------------------
// GEMM. grid 256 = ks*64 + mt. CTA: BM=64 x BN=128, 4 K-chunks of 64:
// [lin p0, sq p0, lin p1, sq p1], pair p covers x-cols ks*128+p*64 .. +64.
// 8 warps (2x4), warp tile 32x32. A and B both generated in-CTA.
// ---------------------------------------------------------------------------
struct MmaCtx {
    uint32_t aBase, bBase;
    float (*acc)[4][4];
};

template <int C>
__device__ __forceinline__ void mma_chunk(const MmaCtx& cx) {
    const uint32_t aA = cx.aBase + C * A_CHUNK;
    const uint32_t bA = cx.bBase + C * B_CHUNK;
    #pragma unroll
    for (int kk = 0; kk < 4; kk++) {
        uint32_t a0[4], a1[4], br0[4], br1[4];
        LDSM4(a0, aA + kk * 32);
        LDSM4(a1, aA + 16 * ROWB + kk * 32);
        LDSM4(br0, bA + kk * 32);
        LDSM4(br1, bA + 16 * ROWB + kk * 32);
        mma16816(cx.acc[0][0], a0, br0[0], br0[1]);
        mma16816(cx.acc[0][1], a0, br0[2], br0[3]);
        mma16816(cx.acc[0][2], a0, br1[0], br1[1]);
        mma16816(cx.acc[0][3], a0, br1[2], br1[3]);
        mma16816(cx.acc[1][0], a1, br0[0], br0[1]);
        mma16816(cx.acc[1][1], a1, br0[2], br0[3]);
        mma16816(cx.acc[1][2], a1, br1[0], br1[1]);
        mma16816(cx.acc[1][3], a1, br1[2], br1[3]);
    }
}

__global__ void __launch_bounds__(256, 2) nb_mma(
    const float* __restrict__ sbjs,
    const float* __restrict__ objs,
    const float* __restrict__ mus,
    const float* __restrict__ sigmas)
{
    extern __shared__ __align__(16) char sm[];

    const int tid  = threadIdx.x;
    const int lane = tid & 31;
    const int wid  = tid >> 5;
    const int wm   = wid >> 2;
    const int wn   = wid & 3;
    const int bid  = blockIdx.x;
    const int mt   = bid & 63;
    const int ks   = bid >> 6;
    const int b0   = mt * 64;

    const uint32_t smb = smem_u32(sm);

    float acc[2][4][4];
    #pragma unroll
    for (int mi = 0; mi < 2; mi++)
        #pragma unroll
        for (int nf = 0; nf < 4; nf++)
            #pragma unroll
            for (int i = 0; i < 4; i++) acc[mi][nf][i] = 0.0f;

    // ---- front-batched fp32 X loads: 8 independent LDG.128 (MLP 8) ----
    const float* __restrict__ xsrc = (ks < 2) ? sbjs : objs;
    const int xb4  = (ks & 1) * 32;
    const int xrow = tid >> 2;
    const int xc4  = (tid & 3) * 4;
    float4 xv[2][4];
    {
        const float4* p = (const float4*)xsrc + (size_t)(b0 + xrow) * 64 + xb4 + xc4;
        #pragma unroll
        for (int j = 0; j < 4; j++) xv[0][j] = p[j];
        #pragma unroll
        for (int j = 0; j < 4; j++) xv[1][j] = p[16 + j];
    }

    // ---- generate B tiles: mu/sigma -> bf16 lin/sq chunks ----
    // 4096 float4 tasks per array: idx -> r = idx>>5, c4 = idx&31.
    // chunk = 2*(c4>>4) (+1 for sq); col byte = (c4&15)*8.
    {
        const float4* mu4 = (const float4*)mus;
        const float4* sg4 = (const float4*)sigmas;
        #pragma unroll
        for (int w = 0; w < 4; w++) {
            float4 mv[4], sv[4];
            #pragma unroll
            for (int j = 0; j < 4; j++) {
                int idx = tid + 256 * (4 * w + j);
                int r = idx >> 5, c4 = idx & 31;
                size_t off = (size_t)r * (TWO_D / 4) + ks * 32 + c4;
                mv[j] = mu4[off];
                sv[j] = sg4[off];
            }
            #pragma unroll
            for (int j = 0; j < 4; j++) {
                int idx = tid + 256 * (4 * w + j);
                int r = idx >> 5, c4 = idx & 31;
                float i0 = __frcp_rn(sv[j].x * sv[j].x);
                float i1 = __frcp_rn(sv[j].y * sv[j].y);
                float i2 = __frcp_rn(sv[j].z * sv[j].z);
                float i3 = __frcp_rn(sv[j].w * sv[j].w);
                uint2 lin, sq;
                lin.x = bf2pack(mv[j].x * i0, mv[j].y * i1);
                lin.y = bf2pack(mv[j].z * i2, mv[j].w * i3);
                sq.x  = bf2pack(-0.5f * i0, -0.5f * i1);
                sq.y  = bf2pack(-0.5f * i2, -0.5f * i3);
                uint32_t base = smb + A_ALL + r * ROWB + (c4 & 15) * 8
                              + ((c4 >> 4) * 2) * B_CHUNK;
                STS8(base, lin);
                STS8(base + B_CHUNK, sq);
            }
        }
    }

    // ---- convert + STS A chunks ----
    {
        const uint32_t abase = smb + xrow * ROWB + (tid & 3) * 32;
        #pragma unroll
        for (int p = 0; p < 2; p++) {
            float4 v0 = xv[p][0], v1 = xv[p][1], v2 = xv[p][2], v3 = xv[p][3];
            uint4 lA, lB, sA_, sB_;
            lA.x = bf2pack(v0.x, v0.y);  lA.y = bf2pack(v0.z, v0.w);
            lA.z = bf2pack(v1.x, v1.y);  lA.w = bf2pack(v1.z, v1.w);
            lB.x = bf2pack(v2.x, v2.y);  lB.y = bf2pack(v2.z, v2.w);
            lB.z = bf2pack(v3.x, v3.y);  lB.w = bf2pack(v3.z, v3.w);
            sA_.x = bf2pack(v0.x * v0.x, v0.y * v0.y);
            sA_.y = bf2pack(v0.z * v0.z, v0.w * v0.w);
            sA_.z = bf2pack(v1.x * v1.x, v1.y * v1.y);
            sA_.w = bf2pack(v1.z * v1.z, v1.w * v1.w);
            sB_.x = bf2pack(v2.x * v2.x, v2.y * v2.y);
            sB_.y = bf2pack(v2.z * v2.z, v2.w * v2.w);
            sB_.z = bf2pack(v3.x * v3.x, v3.y * v3.y);
            sB_.w = bf2pack(v3.z * v3.z, v3.w * v3.w);
            uint32_t aLin = abase + (2 * p) * A_CHUNK;
            uint32_t aSq  = abase + (2 * p + 1) * A_CHUNK;
            STS16(aLin, lA);
            STS16(aLin + 16, lB);
            STS16(aSq, sA_);
            STS16(aSq + 16, sB_);
        }
    }

    // ---- C partials: CTAs mt<8 cover 16 relations each (ks d-range) ----
    if (mt < 8) {
        const int rr    = mt * 16 + (tid >> 4);     // relation
        const int dpart = tid & 15;                 // 8 d's per thread
        const float4* mu4 = (const float4*)mus;
        const float4* sg4 = (const float4*)sigmas;
        size_t off = (size_t)rr * (TWO_D / 4) + ks * 32 + dpart * 2;
        float4 m0 = mu4[off],  m1 = mu4[off + 1];
        float4 s0 = sg4[off],  s1 = sg4[off + 1];
        float cs = 0.0f;
        {
            float mv[8] = {m0.x, m0.y, m0.z, m0.w, m1.x, m1.y, m1.z, m1.w};
            float sv[8] = {s0.x, s0.y, s0.z, s0.w, s1.x, s1.y, s1.z, s1.w};
            #pragma unroll
            for (int j = 0; j < 8; j++) {
                float inv = __frcp_rn(sv[j] * sv[j]);
                cs += fmaf(-0.5f * mv[j], mv[j] * inv, -__logf(sv[j]));
            }
        }
        #pragma unroll
        for (int o = 1; o < 16; o <<= 1)
            cs += __shfl_xor_sync(0xffffffffu, cs, o);
        if (dpart == 0)
            g_Cpart[ks * NREL + rr] = cs;
    }

    __syncthreads();

    MmaCtx cx;
    cx.aBase = smb + (wm * 32 + (lane & 15)) * ROWB + (lane >> 4) * 16;
    cx.bBase = smb + A_ALL
             + (wn * 32 + (lane & 7) + ((lane >> 4) << 3)) * ROWB
             + ((lane >> 3) & 1) * 16;
    cx.acc = acc;

    mma_chunk<0>(cx);
    mma_chunk<1>(cx);
    mma_chunk<2>(cx);
    mma_chunk<3>(cx);

    // ---- epilogue: fp32 partials ----
    float* pout = g_partial + (size_t)ks * (BATCH * NREL);
    #pragma unroll
    for (int mi = 0; mi < 2; mi++) {
        const int r0 = b0 + wm * 32 + mi * 16 + (lane >> 2);
        #pragma unroll
        for (int nf = 0; nf < 4; nf++) {
            const float* a = acc[mi][nf];
            int col = wn * 32 + nf * 8 + (lane & 3) * 2;
            *(float2*)&pout[(size_t)r0 * NREL + col] =
                make_float2(a[0], a[1]);
            *(float2*)&pout[(size_t)(r0 + 8) * NREL + col] =
                make_float2(a[2], a[3]);
        }
    }
}

// ---------------------------------------------------------------------------
// out = sum_ks partial[ks] + C, C = sum_ks Cpart[ks] + 512*prior + K0.
// Fixed order = deterministic.
// ---------------------------------------------------------------------------
__global__ void __launch_bounds__(256) nb_reduce(
    const float* __restrict__ priors, float* __restrict__ out)
{
    const int idx = blockIdx.x * 256 + threadIdx.x;     // float4 index
    const int P   = BATCH * NREL / 4;
    const int rg  = idx & (NREL / 4 - 1);
    const float4* p = (const float4*)g_partial;
    float4 a = p[idx];
    float4 b = p[idx + P];
    float4 c = p[idx + 2 * P];
    float4 d = p[idx + 3 * P];
    float4 c0 = ((const float4*)g_Cpart)[rg];
    float4 c1 = ((const float4*)(g_Cpart + NREL))[rg];
    float4 c2 = ((const float4*)(g_Cpart + 2 * NREL))[rg];
    float4 c3 = ((const float4*)(g_Cpart + 3 * NREL))[rg];
    float4 pr = ((const float4*)priors)[rg];
    const float K0 = -(float)TWO_D * 0.9189385332046727f;
    float4 C;
    C.x = (c0.x + c1.x) + (c2.x + c3.x) + fmaf(pr.x, (float)TWO_D, K0);
    C.y = (c0.y + c1.y) + (c2.y + c3.y) + fmaf(pr.y, (float)TWO_D, K0);
    C.z = (c0.z + c1.z) + (c2.z + c3.z) + fmaf(pr.z, (float)TWO_D, K0);
    C.w = (c0.w + c1.w) + (c2.w + c3.w) + fmaf(pr.w, (float)TWO_D, K0);
    float4 o;
    o.x = (a.x + b.x) + (c.x + d.x) + C.x;
    o.y = (a.y + b.y) + (c.y + d.y) + C.y;
    o.z = (a.z + b.z) + (c.z + d.z) + C.z;
    o.w = (a.w + b.w) + (c.w + d.w) + C.w;
    ((float4*)out)[idx] = o;
}

extern "C" void kernel_launch(void* const* d_in, const int* in_sizes, int n_in,
                              void* d_out, int out_size)
{
    const float* sbjs   = (const float*)d_in[0];
    const float* objs   = (const float*)d_in[1];
    const float* mus    = (const float*)d_in[2];
    const float* sigmas = (const float*)d_in[3];
    const float* priors = (const float*)d_in[4];
    float* out = (float*)d_out;

    cudaFuncSetAttribute(nb_mma,
                         cudaFuncAttributeMaxDynamicSharedMemorySize, SMEM_MMA);

    nb_mma<<<KSPLIT * (BATCH / 64), 256, SMEM_MMA>>>(sbjs, objs, mus, sigmas);
    nb_reduce<<<(BATCH * NREL / 4) / 256, 256>>>(priors, out);
}